// round 5
// baseline (speedup 1.0000x reference)
#include <cuda_runtime.h>
#include <math.h>

#define S_LEN 256
#define B_SZ  16
#define V_SZ  32000
#define E_SZ  512
#define H_SZ  1024
#define M_SZ  (S_LEN * B_SZ)   // 4096

// Scratch (no allocations allowed): x / pred storage and tanh(pred) storage.
__device__ float g_x [M_SZ * H_SZ];   // 16 MB: x[s,b,h] (input projection)
__device__ float g_th[M_SZ * H_SZ];   // 16 MB: tanh(pred[s,b,h])

// ---------------------------------------------------------------------------
// Generic NT SGEMM: C[M,N] = A[M,K] * B[N,K]^T (+ bias[N])
// A optionally gathered through `tokens` (A treated as emb[V,K], row = tokens[m]).
// BM=BN=128, BK=8, 256 threads, 8x8 per-thread register tile, double-buffered.
// Requires M%128==0, N%128==0, K%8==0 (true for all uses here).
// ---------------------------------------------------------------------------
template<bool GATHER>
__global__ void __launch_bounds__(256) sgemm128_nt(
    const float* __restrict__ A,
    const float* __restrict__ B,
    const float* __restrict__ bias,
    const int*   __restrict__ tokens,
    float* __restrict__ C,
    int N, int K)
{
    __shared__ float As[2][8][128];
    __shared__ float Bs[2][8][128];

    const int tid = threadIdx.x;
    const int bm  = blockIdx.y;
    const int bn  = blockIdx.x;

    // global-load mapping: each thread loads one float4 of A and one of B per tile
    const int lrow = tid >> 1;            // 0..127
    const int lk   = (tid & 1) << 2;      // 0 or 4

    const float* Arow;
    if (GATHER) {
        const int tok = tokens[bm * 128 + lrow];
        Arow = A + (size_t)tok * K;
    } else {
        Arow = A + (size_t)(bm * 128 + lrow) * K;
    }
    const float* Brow = B + (size_t)(bn * 128 + lrow) * K;

    const int tx = tid & 15;              // N-direction
    const int ty = tid >> 4;              // M-direction

    float acc[8][8];
#pragma unroll
    for (int i = 0; i < 8; i++)
#pragma unroll
        for (int j = 0; j < 8; j++) acc[i][j] = 0.f;

    // prologue: load tile 0 into buffer 0
    {
        float4 a4 = *(const float4*)(Arow + lk);
        float4 b4 = *(const float4*)(Brow + lk);
        As[0][lk + 0][lrow] = a4.x; As[0][lk + 1][lrow] = a4.y;
        As[0][lk + 2][lrow] = a4.z; As[0][lk + 3][lrow] = a4.w;
        Bs[0][lk + 0][lrow] = b4.x; Bs[0][lk + 1][lrow] = b4.y;
        Bs[0][lk + 2][lrow] = b4.z; Bs[0][lk + 3][lrow] = b4.w;
    }
    __syncthreads();

    const int nt = K >> 3;
    for (int t = 0; t < nt; ++t) {
        const int cur = t & 1;
        float4 na, nb;
        if (t + 1 < nt) {
            na = *(const float4*)(Arow + (t + 1) * 8 + lk);
            nb = *(const float4*)(Brow + (t + 1) * 8 + lk);
        }
#pragma unroll
        for (int k = 0; k < 8; k++) {
            float af[8], bf[8];
            *(float4*)(af)     = *(const float4*)&As[cur][k][ty * 8];
            *(float4*)(af + 4) = *(const float4*)&As[cur][k][ty * 8 + 4];
            *(float4*)(bf)     = *(const float4*)&Bs[cur][k][tx * 8];
            *(float4*)(bf + 4) = *(const float4*)&Bs[cur][k][tx * 8 + 4];
#pragma unroll
            for (int i = 0; i < 8; i++)
#pragma unroll
                for (int j = 0; j < 8; j++)
                    acc[i][j] += af[i] * bf[j];
        }
        if (t + 1 < nt) {
            const int nxt = cur ^ 1;
            As[nxt][lk + 0][lrow] = na.x; As[nxt][lk + 1][lrow] = na.y;
            As[nxt][lk + 2][lrow] = na.z; As[nxt][lk + 3][lrow] = na.w;
            Bs[nxt][lk + 0][lrow] = nb.x; Bs[nxt][lk + 1][lrow] = nb.y;
            Bs[nxt][lk + 2][lrow] = nb.z; Bs[nxt][lk + 3][lrow] = nb.w;
            __syncthreads();
        }
    }

    // epilogue
    const int gm0 = bm * 128 + ty * 8;
    const int gn0 = bn * 128 + tx * 8;
    float bb[8];
    if (bias) {
        *(float4*)(bb)     = *(const float4*)(bias + gn0);
        *(float4*)(bb + 4) = *(const float4*)(bias + gn0 + 4);
    } else {
#pragma unroll
        for (int j = 0; j < 8; j++) bb[j] = 0.f;
    }
#pragma unroll
    for (int i = 0; i < 8; i++) {
        float4 v0, v1;
        v0.x = acc[i][0] + bb[0]; v0.y = acc[i][1] + bb[1];
        v0.z = acc[i][2] + bb[2]; v0.w = acc[i][3] + bb[3];
        v1.x = acc[i][4] + bb[4]; v1.y = acc[i][5] + bb[5];
        v1.z = acc[i][6] + bb[6]; v1.w = acc[i][7] + bb[7];
        float* crow = C + (size_t)(gm0 + i) * N + gn0;
        *(float4*)(crow)     = v0;
        *(float4*)(crow + 4) = v1;
    }
}

// ---------------------------------------------------------------------------
// tanh of x[0] -> th[0]
// ---------------------------------------------------------------------------
__global__ void tanh0_kernel()
{
    int i = blockIdx.x * blockDim.x + threadIdx.x;
    if (i < B_SZ * H_SZ) g_th[i] = tanhf(g_x[i]);
}

// ---------------------------------------------------------------------------
// One recurrence step:
//   th[s][b][n] = tanh( x[s][b][n] + sum_k th[s-1][b][k] * W_hh[n][k] )
// grid = 64 CTAs (16 output columns each), 256 threads = 16b x 16n, 1 out/thread.
// ---------------------------------------------------------------------------
__global__ void __launch_bounds__(256) step_kernel(const float* __restrict__ W_hh, int s)
{
    __shared__ float sA[16][68];   // th_prev tile [b][k], padded (68*4 bytes, 16B aligned rows)
    __shared__ float sW[16][68];   // W_hh tile [n_local][k]

    const float* th_prev = g_th + (size_t)(s - 1) * B_SZ * H_SZ;
    const float* x_s     = g_x  + (size_t)s * B_SZ * H_SZ;
    float*       th_out  = g_th + (size_t)s * B_SZ * H_SZ;

    const int tid = threadIdx.x;
    const int n0  = blockIdx.x * 16;

    const int lr = tid >> 4;          // 0..15 : row for cooperative loads
    const int lc = (tid & 15) << 2;   // 0..60 : float4 column

    const int n = tid & 15;           // output column (local)
    const int b = tid >> 4;           // output batch

    float acc = 0.f;

    for (int kt = 0; kt < H_SZ; kt += 64) {
        float4 a4 = *(const float4*)(th_prev + lr * H_SZ + kt + lc);
        float4 w4 = *(const float4*)(W_hh + (size_t)(n0 + lr) * H_SZ + kt + lc);
        __syncthreads();   // previous iteration's reads must finish
        *(float4*)&sA[lr][lc] = a4;
        *(float4*)&sW[lr][lc] = w4;
        __syncthreads();
#pragma unroll
        for (int k = 0; k < 64; k += 4) {
            float4 av = *(const float4*)&sA[b][k];
            float4 wv = *(const float4*)&sW[n][k];
            acc += av.x * wv.x;
            acc += av.y * wv.y;
            acc += av.z * wv.z;
            acc += av.w * wv.w;
        }
    }

    const int h = n0 + n;
    th_out[b * H_SZ + h] = tanhf(acc + x_s[b * H_SZ + h]);
}

// ---------------------------------------------------------------------------
// kernel_launch
// inputs order: inputs(int32 [S,B]), emb [V,E], W_in [H,E], W_hh [H,H],
//               W_out [V,H], b_out [V]; output: logits fp32 [S*B, V]
// ---------------------------------------------------------------------------
extern "C" void kernel_launch(void* const* d_in, const int* in_sizes, int n_in,
                              void* d_out, int out_size)
{
    (void)in_sizes; (void)n_in; (void)out_size;
    const int*   tokens = (const int*)  d_in[0];
    const float* emb    = (const float*)d_in[1];
    const float* W_in   = (const float*)d_in[2];
    const float* W_hh   = (const float*)d_in[3];
    const float* W_out  = (const float*)d_in[4];
    const float* b_out  = (const float*)d_in[5];
    float* out = (float*)d_out;

    float *gx = nullptr, *gth = nullptr;
    cudaGetSymbolAddress((void**)&gx,  g_x);
    cudaGetSymbolAddress((void**)&gth, g_th);

    // 1) x[s,b,h] = sum_e emb[tok[s,b], e] * W_in[h, e]
    //    M=4096, N=1024, K=512
    sgemm128_nt<true><<<dim3(H_SZ / 128, M_SZ / 128), 256>>>(
        emb, W_in, nullptr, tokens, gx, H_SZ, E_SZ);

    // 2) th[0] = tanh(x[0])
    tanh0_kernel<<<(B_SZ * H_SZ + 255) / 256, 256>>>();

    // 3) recurrence: s = 1..S-1
    for (int s = 1; s < S_LEN; ++s) {
        step_kernel<<<H_SZ / 16, 256>>>(W_hh, s);
    }

    // 4) logits[m, v] = sum_k th[m, k] * W_out[v, k] + b_out[v]
    //    M=4096, N=32000, K=1024
    sgemm128_nt<false><<<dim3(V_SZ / 128, M_SZ / 128), 256>>>(
        gth, W_out, b_out, nullptr, out, V_SZ, H_SZ);
}

// round 6
// speedup vs baseline: 1.0514x; 1.0514x over previous
#include <cuda_runtime.h>
#include <math.h>

#define S_LEN 256
#define B_SZ  16
#define V_SZ  32000
#define E_SZ  512
#define H_SZ  1024
#define M_SZ  (S_LEN * B_SZ)   // 4096

// Scratch (no allocations allowed): x / pred storage and tanh(pred) storage.
__device__ float g_x [M_SZ * H_SZ];   // 16 MB: x[s,b,h] (input projection)
__device__ float g_th[M_SZ * H_SZ];   // 16 MB: tanh(pred[s,b,h])

// ---------------------------------------------------------------------------
// Generic NT SGEMM: C[M,N] = A[M,K] * B[N,K]^T (+ bias[N])
// A optionally gathered through `tokens` (A treated as emb[V,K], row = tokens[m]).
// BM=BN=128, BK=8, 256 threads, 8x8 per-thread register tile, double-buffered.
// Requires M%128==0, N%128==0, K%8==0 (true for all uses here).
// ---------------------------------------------------------------------------
template<bool GATHER>
__global__ void __launch_bounds__(256) sgemm128_nt(
    const float* __restrict__ A,
    const float* __restrict__ B,
    const float* __restrict__ bias,
    const int*   __restrict__ tokens,
    float* __restrict__ C,
    int N, int K)
{
    __shared__ float As[2][8][128];
    __shared__ float Bs[2][8][128];

    const int tid = threadIdx.x;
    const int bm  = blockIdx.y;
    const int bn  = blockIdx.x;

    // global-load mapping: each thread loads one float4 of A and one of B per tile
    const int lrow = tid >> 1;            // 0..127
    const int lk   = (tid & 1) << 2;      // 0 or 4

    const float* Arow;
    if (GATHER) {
        const int tok = tokens[bm * 128 + lrow];
        Arow = A + (size_t)tok * K;
    } else {
        Arow = A + (size_t)(bm * 128 + lrow) * K;
    }
    const float* Brow = B + (size_t)(bn * 128 + lrow) * K;

    const int tx = tid & 15;              // N-direction
    const int ty = tid >> 4;              // M-direction

    float acc[8][8];
#pragma unroll
    for (int i = 0; i < 8; i++)
#pragma unroll
        for (int j = 0; j < 8; j++) acc[i][j] = 0.f;

    // prologue: load tile 0 into buffer 0
    {
        float4 a4 = *(const float4*)(Arow + lk);
        float4 b4 = *(const float4*)(Brow + lk);
        As[0][lk + 0][lrow] = a4.x; As[0][lk + 1][lrow] = a4.y;
        As[0][lk + 2][lrow] = a4.z; As[0][lk + 3][lrow] = a4.w;
        Bs[0][lk + 0][lrow] = b4.x; Bs[0][lk + 1][lrow] = b4.y;
        Bs[0][lk + 2][lrow] = b4.z; Bs[0][lk + 3][lrow] = b4.w;
    }
    __syncthreads();

    const int nt = K >> 3;
    for (int t = 0; t < nt; ++t) {
        const int cur = t & 1;
        float4 na, nb;
        if (t + 1 < nt) {
            na = *(const float4*)(Arow + (t + 1) * 8 + lk);
            nb = *(const float4*)(Brow + (t + 1) * 8 + lk);
        }
#pragma unroll
        for (int k = 0; k < 8; k++) {
            float af[8], bf[8];
            *(float4*)(af)     = *(const float4*)&As[cur][k][ty * 8];
            *(float4*)(af + 4) = *(const float4*)&As[cur][k][ty * 8 + 4];
            *(float4*)(bf)     = *(const float4*)&Bs[cur][k][tx * 8];
            *(float4*)(bf + 4) = *(const float4*)&Bs[cur][k][tx * 8 + 4];
#pragma unroll
            for (int i = 0; i < 8; i++)
#pragma unroll
                for (int j = 0; j < 8; j++)
                    acc[i][j] += af[i] * bf[j];
        }
        if (t + 1 < nt) {
            const int nxt = cur ^ 1;
            As[nxt][lk + 0][lrow] = na.x; As[nxt][lk + 1][lrow] = na.y;
            As[nxt][lk + 2][lrow] = na.z; As[nxt][lk + 3][lrow] = na.w;
            Bs[nxt][lk + 0][lrow] = nb.x; Bs[nxt][lk + 1][lrow] = nb.y;
            Bs[nxt][lk + 2][lrow] = nb.z; Bs[nxt][lk + 3][lrow] = nb.w;
            __syncthreads();
        }
    }

    // epilogue
    const int gm0 = bm * 128 + ty * 8;
    const int gn0 = bn * 128 + tx * 8;
    float bb[8];
    if (bias) {
        *(float4*)(bb)     = *(const float4*)(bias + gn0);
        *(float4*)(bb + 4) = *(const float4*)(bias + gn0 + 4);
    } else {
#pragma unroll
        for (int j = 0; j < 8; j++) bb[j] = 0.f;
    }
#pragma unroll
    for (int i = 0; i < 8; i++) {
        float4 v0, v1;
        v0.x = acc[i][0] + bb[0]; v0.y = acc[i][1] + bb[1];
        v0.z = acc[i][2] + bb[2]; v0.w = acc[i][3] + bb[3];
        v1.x = acc[i][4] + bb[4]; v1.y = acc[i][5] + bb[5];
        v1.z = acc[i][6] + bb[6]; v1.w = acc[i][7] + bb[7];
        float* crow = C + (size_t)(gm0 + i) * N + gn0;
        *(float4*)(crow)     = v0;
        *(float4*)(crow + 4) = v1;
    }
}

// ---------------------------------------------------------------------------
// tanh of x[0] -> th[0]
// ---------------------------------------------------------------------------
__global__ void tanh0_kernel()
{
    int i = blockIdx.x * blockDim.x + threadIdx.x;
    if (i < B_SZ * H_SZ) g_th[i] = tanhf(g_x[i]);
}

// ---------------------------------------------------------------------------
// One recurrence step:
//   th[s][b][n] = tanh( x[s][b][n] + sum_k th[s-1][b][k] * W_hh[n][k] )
// grid = 64 CTAs (16 output columns each), 256 threads = 16b x 16n, 1 out/thread.
// ---------------------------------------------------------------------------
__global__ void __launch_bounds__(256) step_kernel(const float* __restrict__ W_hh, int s)
{
    __shared__ float sA[16][68];   // th_prev tile [b][k], padded (68*4 bytes, 16B aligned rows)
    __shared__ float sW[16][68];   // W_hh tile [n_local][k]

    const float* th_prev = g_th + (size_t)(s - 1) * B_SZ * H_SZ;
    const float* x_s     = g_x  + (size_t)s * B_SZ * H_SZ;
    float*       th_out  = g_th + (size_t)s * B_SZ * H_SZ;

    const int tid = threadIdx.x;
    const int n0  = blockIdx.x * 16;

    const int lr = tid >> 4;          // 0..15 : row for cooperative loads
    const int lc = (tid & 15) << 2;   // 0..60 : float4 column

    const int n = tid & 15;           // output column (local)
    const int b = tid >> 4;           // output batch

    float acc = 0.f;

    for (int kt = 0; kt < H_SZ; kt += 64) {
        float4 a4 = *(const float4*)(th_prev + lr * H_SZ + kt + lc);
        float4 w4 = *(const float4*)(W_hh + (size_t)(n0 + lr) * H_SZ + kt + lc);
        __syncthreads();   // previous iteration's reads must finish
        *(float4*)&sA[lr][lc] = a4;
        *(float4*)&sW[lr][lc] = w4;
        __syncthreads();
#pragma unroll
        for (int k = 0; k < 64; k += 4) {
            float4 av = *(const float4*)&sA[b][k];
            float4 wv = *(const float4*)&sW[n][k];
            acc += av.x * wv.x;
            acc += av.y * wv.y;
            acc += av.z * wv.z;
            acc += av.w * wv.w;
        }
    }

    const int h = n0 + n;
    th_out[b * H_SZ + h] = tanhf(acc + x_s[b * H_SZ + h]);
}

// ---------------------------------------------------------------------------
// kernel_launch
// inputs order: inputs(int32 [S,B]), emb [V,E], W_in [H,E], W_hh [H,H],
//               W_out [V,H], b_out [V]; output: logits fp32 [S*B, V]
// ---------------------------------------------------------------------------
extern "C" void kernel_launch(void* const* d_in, const int* in_sizes, int n_in,
                              void* d_out, int out_size)
{
    (void)in_sizes; (void)n_in; (void)out_size;
    const int*   tokens = (const int*)  d_in[0];
    const float* emb    = (const float*)d_in[1];
    const float* W_in   = (const float*)d_in[2];
    const float* W_hh   = (const float*)d_in[3];
    const float* W_out  = (const float*)d_in[4];
    const float* b_out  = (const float*)d_in[5];
    float* out = (float*)d_out;

    float *gx = nullptr, *gth = nullptr;
    cudaGetSymbolAddress((void**)&gx,  g_x);
    cudaGetSymbolAddress((void**)&gth, g_th);

    // 1) x[s,b,h] = sum_e emb[tok[s,b], e] * W_in[h, e]
    //    M=4096, N=1024, K=512
    sgemm128_nt<true><<<dim3(H_SZ / 128, M_SZ / 128), 256>>>(
        emb, W_in, nullptr, tokens, gx, H_SZ, E_SZ);

    // 2) th[0] = tanh(x[0])
    tanh0_kernel<<<(B_SZ * H_SZ + 255) / 256, 256>>>();

    // 3) recurrence: s = 1..S-1
    for (int s = 1; s < S_LEN; ++s) {
        step_kernel<<<H_SZ / 16, 256>>>(W_hh, s);
    }

    // 4) logits[m, v] = sum_k th[m, k] * W_out[v, k] + b_out[v]
    //    M=4096, N=32000, K=1024
    sgemm128_nt<false><<<dim3(V_SZ / 128, M_SZ / 128), 256>>>(
        gth, W_out, b_out, nullptr, out, V_SZ, H_SZ);
}

// round 7
// speedup vs baseline: 1.0521x; 1.0006x over previous
#include <cuda_runtime.h>
#include <math.h>

#define S_LEN 256
#define B_SZ  16
#define V_SZ  32000
#define E_SZ  512
#define H_SZ  1024
#define M_SZ  (S_LEN * B_SZ)   // 4096

// Scratch (no allocations allowed): x / pred storage and tanh(pred) storage.
__device__ float g_x [M_SZ * H_SZ];   // 16 MB: x[s,b,h] (input projection)
__device__ float g_th[M_SZ * H_SZ];   // 16 MB: tanh(pred[s,b,h])

// ---------------------------------------------------------------------------
// Generic NT SGEMM: C[M,N] = A[M,K] * B[N,K]^T (+ bias[N])
// A optionally gathered through `tokens` (A treated as emb[V,K], row = tokens[m]).
// BM=BN=128, BK=8, 256 threads, 8x8 per-thread register tile, double-buffered.
// Requires M%128==0, N%128==0, K%8==0 (true for all uses here).
// ---------------------------------------------------------------------------
template<bool GATHER>
__global__ void __launch_bounds__(256) sgemm128_nt(
    const float* __restrict__ A,
    const float* __restrict__ B,
    const float* __restrict__ bias,
    const int*   __restrict__ tokens,
    float* __restrict__ C,
    int N, int K)
{
    __shared__ float As[2][8][128];
    __shared__ float Bs[2][8][128];

    const int tid = threadIdx.x;
    const int bm  = blockIdx.y;
    const int bn  = blockIdx.x;

    // global-load mapping: each thread loads one float4 of A and one of B per tile
    const int lrow = tid >> 1;            // 0..127
    const int lk   = (tid & 1) << 2;      // 0 or 4

    const float* Arow;
    if (GATHER) {
        const int tok = tokens[bm * 128 + lrow];
        Arow = A + (size_t)tok * K;
    } else {
        Arow = A + (size_t)(bm * 128 + lrow) * K;
    }
    const float* Brow = B + (size_t)(bn * 128 + lrow) * K;

    const int tx = tid & 15;              // N-direction
    const int ty = tid >> 4;              // M-direction

    float acc[8][8];
#pragma unroll
    for (int i = 0; i < 8; i++)
#pragma unroll
        for (int j = 0; j < 8; j++) acc[i][j] = 0.f;

    // prologue: load tile 0 into buffer 0
    {
        float4 a4 = *(const float4*)(Arow + lk);
        float4 b4 = *(const float4*)(Brow + lk);
        As[0][lk + 0][lrow] = a4.x; As[0][lk + 1][lrow] = a4.y;
        As[0][lk + 2][lrow] = a4.z; As[0][lk + 3][lrow] = a4.w;
        Bs[0][lk + 0][lrow] = b4.x; Bs[0][lk + 1][lrow] = b4.y;
        Bs[0][lk + 2][lrow] = b4.z; Bs[0][lk + 3][lrow] = b4.w;
    }
    __syncthreads();

    const int nt = K >> 3;
    for (int t = 0; t < nt; ++t) {
        const int cur = t & 1;
        float4 na, nb;
        if (t + 1 < nt) {
            na = *(const float4*)(Arow + (t + 1) * 8 + lk);
            nb = *(const float4*)(Brow + (t + 1) * 8 + lk);
        }
#pragma unroll
        for (int k = 0; k < 8; k++) {
            float af[8], bf[8];
            *(float4*)(af)     = *(const float4*)&As[cur][k][ty * 8];
            *(float4*)(af + 4) = *(const float4*)&As[cur][k][ty * 8 + 4];
            *(float4*)(bf)     = *(const float4*)&Bs[cur][k][tx * 8];
            *(float4*)(bf + 4) = *(const float4*)&Bs[cur][k][tx * 8 + 4];
#pragma unroll
            for (int i = 0; i < 8; i++)
#pragma unroll
                for (int j = 0; j < 8; j++)
                    acc[i][j] += af[i] * bf[j];
        }
        if (t + 1 < nt) {
            const int nxt = cur ^ 1;
            As[nxt][lk + 0][lrow] = na.x; As[nxt][lk + 1][lrow] = na.y;
            As[nxt][lk + 2][lrow] = na.z; As[nxt][lk + 3][lrow] = na.w;
            Bs[nxt][lk + 0][lrow] = nb.x; Bs[nxt][lk + 1][lrow] = nb.y;
            Bs[nxt][lk + 2][lrow] = nb.z; Bs[nxt][lk + 3][lrow] = nb.w;
            __syncthreads();
        }
    }

    // epilogue
    const int gm0 = bm * 128 + ty * 8;
    const int gn0 = bn * 128 + tx * 8;
    float bb[8];
    if (bias) {
        *(float4*)(bb)     = *(const float4*)(bias + gn0);
        *(float4*)(bb + 4) = *(const float4*)(bias + gn0 + 4);
    } else {
#pragma unroll
        for (int j = 0; j < 8; j++) bb[j] = 0.f;
    }
#pragma unroll
    for (int i = 0; i < 8; i++) {
        float4 v0, v1;
        v0.x = acc[i][0] + bb[0]; v0.y = acc[i][1] + bb[1];
        v0.z = acc[i][2] + bb[2]; v0.w = acc[i][3] + bb[3];
        v1.x = acc[i][4] + bb[4]; v1.y = acc[i][5] + bb[5];
        v1.z = acc[i][6] + bb[6]; v1.w = acc[i][7] + bb[7];
        float* crow = C + (size_t)(gm0 + i) * N + gn0;
        *(float4*)(crow)     = v0;
        *(float4*)(crow + 4) = v1;
    }
}

// ---------------------------------------------------------------------------
// tanh of x[0] -> th[0]
// ---------------------------------------------------------------------------
__global__ void tanh0_kernel()
{
    int i = blockIdx.x * blockDim.x + threadIdx.x;
    if (i < B_SZ * H_SZ) g_th[i] = tanhf(g_x[i]);
}

// ---------------------------------------------------------------------------
// One recurrence step:
//   th[s][b][n] = tanh( x[s][b][n] + sum_k th[s-1][b][k] * W_hh[n][k] )
// grid = 64 CTAs (16 output columns each), 256 threads = 16b x 16n, 1 out/thread.
// ---------------------------------------------------------------------------
__global__ void __launch_bounds__(256) step_kernel(const float* __restrict__ W_hh, int s)
{
    __shared__ float sA[16][68];   // th_prev tile [b][k], padded (68*4 bytes, 16B aligned rows)
    __shared__ float sW[16][68];   // W_hh tile [n_local][k]

    const float* th_prev = g_th + (size_t)(s - 1) * B_SZ * H_SZ;
    const float* x_s     = g_x  + (size_t)s * B_SZ * H_SZ;
    float*       th_out  = g_th + (size_t)s * B_SZ * H_SZ;

    const int tid = threadIdx.x;
    const int n0  = blockIdx.x * 16;

    const int lr = tid >> 4;          // 0..15 : row for cooperative loads
    const int lc = (tid & 15) << 2;   // 0..60 : float4 column

    const int n = tid & 15;           // output column (local)
    const int b = tid >> 4;           // output batch

    float acc = 0.f;

    for (int kt = 0; kt < H_SZ; kt += 64) {
        float4 a4 = *(const float4*)(th_prev + lr * H_SZ + kt + lc);
        float4 w4 = *(const float4*)(W_hh + (size_t)(n0 + lr) * H_SZ + kt + lc);
        __syncthreads();   // previous iteration's reads must finish
        *(float4*)&sA[lr][lc] = a4;
        *(float4*)&sW[lr][lc] = w4;
        __syncthreads();
#pragma unroll
        for (int k = 0; k < 64; k += 4) {
            float4 av = *(const float4*)&sA[b][k];
            float4 wv = *(const float4*)&sW[n][k];
            acc += av.x * wv.x;
            acc += av.y * wv.y;
            acc += av.z * wv.z;
            acc += av.w * wv.w;
        }
    }

    const int h = n0 + n;
    th_out[b * H_SZ + h] = tanhf(acc + x_s[b * H_SZ + h]);
}

// ---------------------------------------------------------------------------
// kernel_launch
// inputs order: inputs(int32 [S,B]), emb [V,E], W_in [H,E], W_hh [H,H],
//               W_out [V,H], b_out [V]; output: logits fp32 [S*B, V]
// ---------------------------------------------------------------------------
extern "C" void kernel_launch(void* const* d_in, const int* in_sizes, int n_in,
                              void* d_out, int out_size)
{
    (void)in_sizes; (void)n_in; (void)out_size;
    const int*   tokens = (const int*)  d_in[0];
    const float* emb    = (const float*)d_in[1];
    const float* W_in   = (const float*)d_in[2];
    const float* W_hh   = (const float*)d_in[3];
    const float* W_out  = (const float*)d_in[4];
    const float* b_out  = (const float*)d_in[5];
    float* out = (float*)d_out;

    float *gx = nullptr, *gth = nullptr;
    cudaGetSymbolAddress((void**)&gx,  g_x);
    cudaGetSymbolAddress((void**)&gth, g_th);

    // 1) x[s,b,h] = sum_e emb[tok[s,b], e] * W_in[h, e]
    //    M=4096, N=1024, K=512
    sgemm128_nt<true><<<dim3(H_SZ / 128, M_SZ / 128), 256>>>(
        emb, W_in, nullptr, tokens, gx, H_SZ, E_SZ);

    // 2) th[0] = tanh(x[0])
    tanh0_kernel<<<(B_SZ * H_SZ + 255) / 256, 256>>>();

    // 3) recurrence: s = 1..S-1
    for (int s = 1; s < S_LEN; ++s) {
        step_kernel<<<H_SZ / 16, 256>>>(W_hh, s);
    }

    // 4) logits[m, v] = sum_k th[m, k] * W_out[v, k] + b_out[v]
    //    M=4096, N=32000, K=1024
    sgemm128_nt<false><<<dim3(V_SZ / 128, M_SZ / 128), 256>>>(
        gth, W_out, b_out, nullptr, out, V_SZ, H_SZ);
}

// round 8
// speedup vs baseline: 1.4089x; 1.3391x over previous
#include <cuda_runtime.h>
#include <math.h>

#define S_LEN 256
#define B_SZ  16
#define V_SZ  32000
#define E_SZ  512
#define H_SZ  1024
#define M_SZ  (S_LEN * B_SZ)   // 4096

// Scratch (no allocations allowed)
__device__ float    g_x [M_SZ * H_SZ];   // 16 MB: x[s,b,h]
__device__ float    g_th[M_SZ * H_SZ];   // 16 MB: tanh(pred[s,b,h])
__device__ unsigned g_bar;               // software grid barrier counter

// ---------------------------------------------------------------------------
// Generic NT SGEMM: C[M,N] = A[M,K] * B[N,K]^T (+ bias[N]), f32x2-packed FMAs.
// BM=BN=128, BK=8, 256 threads, 8x8 per-thread tile, double-buffered smem.
// ---------------------------------------------------------------------------
template<bool GATHER>
__global__ void __launch_bounds__(256) sgemm128_nt(
    const float* __restrict__ A,
    const float* __restrict__ B,
    const float* __restrict__ bias,
    const int*   __restrict__ tokens,
    float* __restrict__ C,
    int N, int K)
{
    __shared__ float As[2][8][128];
    __shared__ float Bs[2][8][128];

    const int tid = threadIdx.x;
    const int bm  = blockIdx.y;
    const int bn  = blockIdx.x;

    const int lrow = tid >> 1;            // 0..127
    const int lk   = (tid & 1) << 2;      // 0 or 4

    const float* Arow;
    if (GATHER) {
        const int tok = tokens[bm * 128 + lrow];
        Arow = A + (size_t)tok * K;
    } else {
        Arow = A + (size_t)(bm * 128 + lrow) * K;
    }
    const float* Brow = B + (size_t)(bn * 128 + lrow) * K;

    const int tx = tid & 15;              // N-direction
    const int ty = tid >> 4;              // M-direction

    // packed accumulators: acc2[i][jp] holds (acc[i][2jp], acc[i][2jp+1])
    unsigned long long acc2[8][4];
#pragma unroll
    for (int i = 0; i < 8; i++)
#pragma unroll
        for (int jp = 0; jp < 4; jp++) acc2[i][jp] = 0ull;  // (+0.0f, +0.0f)

    // prologue: tile 0 -> buffer 0
    {
        float4 a4 = *(const float4*)(Arow + lk);
        float4 b4 = *(const float4*)(Brow + lk);
        As[0][lk + 0][lrow] = a4.x; As[0][lk + 1][lrow] = a4.y;
        As[0][lk + 2][lrow] = a4.z; As[0][lk + 3][lrow] = a4.w;
        Bs[0][lk + 0][lrow] = b4.x; Bs[0][lk + 1][lrow] = b4.y;
        Bs[0][lk + 2][lrow] = b4.z; Bs[0][lk + 3][lrow] = b4.w;
    }
    __syncthreads();

    const int nt = K >> 3;
    for (int t = 0; t < nt; ++t) {
        const int cur = t & 1;
        float4 na, nb;
        if (t + 1 < nt) {
            na = *(const float4*)(Arow + (t + 1) * 8 + lk);
            nb = *(const float4*)(Brow + (t + 1) * 8 + lk);
        }
#pragma unroll
        for (int k = 0; k < 8; k++) {
            float af[8];
            *(float4*)(af)     = *(const float4*)&As[cur][k][ty * 8];
            *(float4*)(af + 4) = *(const float4*)&As[cur][k][ty * 8 + 4];
            ulonglong2 b01 = *(const ulonglong2*)&Bs[cur][k][tx * 8];
            ulonglong2 b23 = *(const ulonglong2*)&Bs[cur][k][tx * 8 + 4];
#pragma unroll
            for (int i = 0; i < 8; i++) {
                unsigned long long ai;
                asm("mov.b64 %0, {%1, %1};" : "=l"(ai) : "f"(af[i]));
                asm("fma.rn.f32x2 %0, %1, %2, %0;" : "+l"(acc2[i][0]) : "l"(ai), "l"(b01.x));
                asm("fma.rn.f32x2 %0, %1, %2, %0;" : "+l"(acc2[i][1]) : "l"(ai), "l"(b01.y));
                asm("fma.rn.f32x2 %0, %1, %2, %0;" : "+l"(acc2[i][2]) : "l"(ai), "l"(b23.x));
                asm("fma.rn.f32x2 %0, %1, %2, %0;" : "+l"(acc2[i][3]) : "l"(ai), "l"(b23.y));
            }
        }
        if (t + 1 < nt) {
            const int nxt = cur ^ 1;
            As[nxt][lk + 0][lrow] = na.x; As[nxt][lk + 1][lrow] = na.y;
            As[nxt][lk + 2][lrow] = na.z; As[nxt][lk + 3][lrow] = na.w;
            Bs[nxt][lk + 0][lrow] = nb.x; Bs[nxt][lk + 1][lrow] = nb.y;
            Bs[nxt][lk + 2][lrow] = nb.z; Bs[nxt][lk + 3][lrow] = nb.w;
            __syncthreads();
        }
    }

    // epilogue
    const int gm0 = bm * 128 + ty * 8;
    const int gn0 = bn * 128 + tx * 8;
    float bb[8];
    if (bias) {
        *(float4*)(bb)     = *(const float4*)(bias + gn0);
        *(float4*)(bb + 4) = *(const float4*)(bias + gn0 + 4);
    } else {
#pragma unroll
        for (int j = 0; j < 8; j++) bb[j] = 0.f;
    }
#pragma unroll
    for (int i = 0; i < 8; i++) {
        float cv[8];
#pragma unroll
        for (int jp = 0; jp < 4; jp++) {
            float lo, hi;
            asm("mov.b64 {%0, %1}, %2;" : "=f"(lo), "=f"(hi) : "l"(acc2[i][jp]));
            cv[2 * jp]     = lo + bb[2 * jp];
            cv[2 * jp + 1] = hi + bb[2 * jp + 1];
        }
        float* crow = C + (size_t)(gm0 + i) * N + gn0;
        *(float4*)(crow)     = *(float4*)(cv);
        *(float4*)(crow + 4) = *(float4*)(cv + 4);
    }
}

// ---------------------------------------------------------------------------
// init: th[0] = tanh(x[0]); reset grid-barrier counter (graph-replay safe)
// ---------------------------------------------------------------------------
__global__ void __launch_bounds__(256) init_kernel()
{
    int i = blockIdx.x * blockDim.x + threadIdx.x;
    if (i < B_SZ * H_SZ) g_th[i] = tanhf(g_x[i]);
    if (i == 0) g_bar = 0u;
}

// ---------------------------------------------------------------------------
// Persistent recurrence scan: one kernel, 64 CTAs (all wave-1 co-resident),
// software grid barrier between steps. W_hh cached in REGISTERS (f32x2 pairs):
// thread (n = tid&15, kc = tid>>4) owns W_hh[n0+n][kc*64 .. kc*64+63].
//   th[s][b][n] = tanh( x[s][b][n] + sum_k th[s-1][b][k] * W_hh[n][k] )
// ---------------------------------------------------------------------------
extern __shared__ float smem_dyn[];

__global__ void __launch_bounds__(256) rnn_scan_kernel(const float* __restrict__ W_hh)
{
    float* sh_th = smem_dyn;             // [16][1024] = 64 KB
    float* psum  = smem_dyn + 16 * 1024; // [kc=16][b=16][n=16] = 16 KB

    const int tid = threadIdx.x;
    const int n   = tid & 15;            // local output column
    const int kc  = tid >> 4;            // k-chunk (64 wide)
    const int n0  = blockIdx.x * 16;

    // Load this thread's W slice into registers, packed as f32x2 pairs.
    unsigned long long wq[32];
    {
        const ulonglong2* wp =
            (const ulonglong2*)(W_hh + (size_t)(n0 + n) * H_SZ + kc * 64);
#pragma unroll
        for (int t = 0; t < 16; ++t) {
            ulonglong2 u = wp[t];
            wq[2 * t]     = u.x;
            wq[2 * t + 1] = u.y;
        }
    }

    const int rb = tid >> 4;   // reduction-phase batch index
    const int rn = tid & 15;   // reduction-phase column index

    unsigned* barp = &g_bar;

    for (int s = 1; s < S_LEN; ++s) {
        // Ensure all smem reads of previous iteration are done before reuse.
        __syncthreads();

        // Grid barrier: wait until all 64 CTAs finished step s-1 global writes.
        if (tid == 0) {
            __threadfence();
            atomicAdd(barp, 1u);
            const unsigned target = 64u * (unsigned)s;
            unsigned v;
            do {
                asm volatile("ld.acquire.gpu.u32 %0, [%1];" : "=r"(v) : "l"(barp));
            } while (v < target);
        }
        __syncthreads();

        // Prefetch x for this thread's output (used late -> latency hidden).
        const float xv = g_x[(size_t)s * B_SZ * H_SZ + rb * H_SZ + n0 + rn];

        // Cooperative load th[s-1] (64 KB) into smem, coalesced.
        {
            const float4* src = (const float4*)(g_th + (size_t)(s - 1) * B_SZ * H_SZ);
            float4* dst = (float4*)sh_th;
#pragma unroll
            for (int t = 0; t < 16; ++t)
                dst[tid + 256 * t] = src[tid + 256 * t];
        }
        __syncthreads();

        // Partial dot products: for each b, over this thread's 64-wide k-chunk.
#pragma unroll 1
        for (int b = 0; b < 16; ++b) {
            const ulonglong2* tp = (const ulonglong2*)(sh_th + b * H_SZ + kc * 64);
            unsigned long long s0 = 0ull, s1 = 0ull;
#pragma unroll
            for (int t = 0; t < 16; ++t) {
                ulonglong2 u = tp[t];
                asm("fma.rn.f32x2 %0, %1, %2, %0;" : "+l"(s0) : "l"(wq[2 * t]),     "l"(u.x));
                asm("fma.rn.f32x2 %0, %1, %2, %0;" : "+l"(s1) : "l"(wq[2 * t + 1]), "l"(u.y));
            }
            float p0, p1, p2, p3;
            asm("mov.b64 {%0, %1}, %2;" : "=f"(p0), "=f"(p1) : "l"(s0));
            asm("mov.b64 {%0, %1}, %2;" : "=f"(p2), "=f"(p3) : "l"(s1));
            psum[kc * 256 + b * 16 + n] = (p0 + p1) + (p2 + p3);
        }
        __syncthreads();

        // Reduce over the 16 k-chunks, add x, tanh, store to global.
        float acc = xv;
#pragma unroll
        for (int k2 = 0; k2 < 16; ++k2)
            acc += psum[k2 * 256 + rb * 16 + rn];
        g_th[(size_t)s * B_SZ * H_SZ + rb * H_SZ + n0 + rn] = tanhf(acc);
    }
}

// ---------------------------------------------------------------------------
// kernel_launch
// ---------------------------------------------------------------------------
extern "C" void kernel_launch(void* const* d_in, const int* in_sizes, int n_in,
                              void* d_out, int out_size)
{
    (void)in_sizes; (void)n_in; (void)out_size;
    const int*   tokens = (const int*)  d_in[0];
    const float* emb    = (const float*)d_in[1];
    const float* W_in   = (const float*)d_in[2];
    const float* W_hh   = (const float*)d_in[3];
    const float* W_out  = (const float*)d_in[4];
    const float* b_out  = (const float*)d_in[5];
    float* out = (float*)d_out;

    float *gx = nullptr, *gth = nullptr;
    cudaGetSymbolAddress((void**)&gx,  g_x);
    cudaGetSymbolAddress((void**)&gth, g_th);

    // 1) x[s,b,h] = sum_e emb[tok[s,b], e] * W_in[h, e]   (M=4096,N=1024,K=512)
    sgemm128_nt<true><<<dim3(H_SZ / 128, M_SZ / 128), 256>>>(
        emb, W_in, nullptr, tokens, gx, H_SZ, E_SZ);

    // 2) th[0] = tanh(x[0]); reset barrier
    init_kernel<<<(B_SZ * H_SZ + 255) / 256, 256>>>();

    // 3) persistent recurrence over s = 1..255
    const int scan_smem = (16 * 1024 + 16 * 16 * 16) * (int)sizeof(float); // 80 KB
    cudaFuncSetAttribute(rnn_scan_kernel,
                         cudaFuncAttributeMaxDynamicSharedMemorySize, scan_smem);
    rnn_scan_kernel<<<H_SZ / 16, 256, scan_smem>>>(W_hh);

    // 4) logits = th @ W_out^T + b_out   (M=4096, N=32000, K=1024)
    sgemm128_nt<false><<<dim3(V_SZ / 128, M_SZ / 128), 256>>>(
        gth, W_out, b_out, nullptr, out, V_SZ, H_SZ);
}

// round 11
// speedup vs baseline: 3.1990x; 2.2707x over previous
#include <cuda_runtime.h>
#include <cuda_bf16.h>
#include <math.h>
#include <stdint.h>

#define S_LEN 256
#define B_SZ  16
#define V_SZ  32000
#define E_SZ  512
#define H_SZ  1024
#define M_SZ  (S_LEN * B_SZ)   // 4096

// ---------------------------------------------------------------------------
// Device scratch (static — no runtime allocation allowed)
// ---------------------------------------------------------------------------
__device__ float    g_x [M_SZ * H_SZ];
__device__ float    g_th[M_SZ * H_SZ];
__device__ unsigned g_bar;
__device__ __align__(16) __nv_bfloat16 g_th_hi[M_SZ * H_SZ];
__device__ __align__(16) __nv_bfloat16 g_th_lo[M_SZ * H_SZ];
__device__ __align__(16) __nv_bfloat16 g_wo_hi[(size_t)V_SZ * H_SZ];
__device__ __align__(16) __nv_bfloat16 g_wo_lo[(size_t)V_SZ * H_SZ];

#define SMEM_SWIZZLE_128B(o) ((o) ^ (((o) >> 3) & 0x70))

__device__ __forceinline__ uint32_t smem_to_u32(const void* p) {
    uint32_t a;
    asm("{ .reg .u64 t; cvta.to.shared.u64 t, %1; cvt.u32.u64 %0, t; }"
        : "=r"(a) : "l"(p));
    return a;
}

__device__ __forceinline__ void cp16(uint32_t saddr, const void* g) {
    unsigned long long ga = (unsigned long long)__cvta_generic_to_global(g);
    asm volatile("cp.async.cg.shared.global [%0], [%1], 16;"
                 :: "r"(saddr), "l"(ga) : "memory");
}
__device__ __forceinline__ void cp_commit() {
    asm volatile("cp.async.commit_group;" ::: "memory");
}
template<int N>
__device__ __forceinline__ void cp_wait() {
    asm volatile("cp.async.wait_group %0;" :: "n"(N) : "memory");
}

__device__ __forceinline__ void ldsm_x4(uint32_t* r, uint32_t addr) {
    asm volatile("ldmatrix.sync.aligned.m8n8.x4.shared.b16 {%0,%1,%2,%3}, [%4];"
                 : "=r"(r[0]), "=r"(r[1]), "=r"(r[2]), "=r"(r[3]) : "r"(addr));
}
__device__ __forceinline__ void mma16816(float* d, const uint32_t* a, const uint32_t* b) {
    asm volatile(
        "mma.sync.aligned.m16n8k16.row.col.f32.bf16.bf16.f32 "
        "{%0,%1,%2,%3}, {%4,%5,%6,%7}, {%8,%9}, {%0,%1,%2,%3};"
        : "+f"(d[0]), "+f"(d[1]), "+f"(d[2]), "+f"(d[3])
        : "r"(a[0]), "r"(a[1]), "r"(a[2]), "r"(a[3]), "r"(b[0]), "r"(b[1]));
}

// ---------------------------------------------------------------------------
// Scalar NT SGEMM (f32x2) — input projection only (M=4096,N=1024,K=512)
// ---------------------------------------------------------------------------
template<bool GATHER>
__global__ void __launch_bounds__(256) sgemm128_nt(
    const float* __restrict__ A,
    const float* __restrict__ B,
    const float* __restrict__ bias,
    const int*   __restrict__ tokens,
    float* __restrict__ C,
    int N, int K)
{
    __shared__ float As[2][8][128];
    __shared__ float Bs[2][8][128];

    const int tid = threadIdx.x;
    const int bm  = blockIdx.y;
    const int bn  = blockIdx.x;

    const int lrow = tid >> 1;
    const int lk   = (tid & 1) << 2;

    const float* Arow;
    if (GATHER) {
        const int tok = tokens[bm * 128 + lrow];
        Arow = A + (size_t)tok * K;
    } else {
        Arow = A + (size_t)(bm * 128 + lrow) * K;
    }
    const float* Brow = B + (size_t)(bn * 128 + lrow) * K;

    const int tx = tid & 15;
    const int ty = tid >> 4;

    unsigned long long acc2[8][4];
#pragma unroll
    for (int i = 0; i < 8; i++)
#pragma unroll
        for (int jp = 0; jp < 4; jp++) acc2[i][jp] = 0ull;

    {
        float4 a4 = *(const float4*)(Arow + lk);
        float4 b4 = *(const float4*)(Brow + lk);
        As[0][lk + 0][lrow] = a4.x; As[0][lk + 1][lrow] = a4.y;
        As[0][lk + 2][lrow] = a4.z; As[0][lk + 3][lrow] = a4.w;
        Bs[0][lk + 0][lrow] = b4.x; Bs[0][lk + 1][lrow] = b4.y;
        Bs[0][lk + 2][lrow] = b4.z; Bs[0][lk + 3][lrow] = b4.w;
    }
    __syncthreads();

    const int nt = K >> 3;
    for (int t = 0; t < nt; ++t) {
        const int cur = t & 1;
        float4 na, nb;
        if (t + 1 < nt) {
            na = *(const float4*)(Arow + (t + 1) * 8 + lk);
            nb = *(const float4*)(Brow + (t + 1) * 8 + lk);
        }
#pragma unroll
        for (int k = 0; k < 8; k++) {
            float af[8];
            *(float4*)(af)     = *(const float4*)&As[cur][k][ty * 8];
            *(float4*)(af + 4) = *(const float4*)&As[cur][k][ty * 8 + 4];
            ulonglong2 b01 = *(const ulonglong2*)&Bs[cur][k][tx * 8];
            ulonglong2 b23 = *(const ulonglong2*)&Bs[cur][k][tx * 8 + 4];
#pragma unroll
            for (int i = 0; i < 8; i++) {
                unsigned long long ai;
                asm("mov.b64 %0, {%1, %1};" : "=l"(ai) : "f"(af[i]));
                asm("fma.rn.f32x2 %0, %1, %2, %0;" : "+l"(acc2[i][0]) : "l"(ai), "l"(b01.x));
                asm("fma.rn.f32x2 %0, %1, %2, %0;" : "+l"(acc2[i][1]) : "l"(ai), "l"(b01.y));
                asm("fma.rn.f32x2 %0, %1, %2, %0;" : "+l"(acc2[i][2]) : "l"(ai), "l"(b23.x));
                asm("fma.rn.f32x2 %0, %1, %2, %0;" : "+l"(acc2[i][3]) : "l"(ai), "l"(b23.y));
            }
        }
        if (t + 1 < nt) {
            const int nxt = cur ^ 1;
            As[nxt][lk + 0][lrow] = na.x; As[nxt][lk + 1][lrow] = na.y;
            As[nxt][lk + 2][lrow] = na.z; As[nxt][lk + 3][lrow] = na.w;
            Bs[nxt][lk + 0][lrow] = nb.x; Bs[nxt][lk + 1][lrow] = nb.y;
            Bs[nxt][lk + 2][lrow] = nb.z; Bs[nxt][lk + 3][lrow] = nb.w;
            __syncthreads();
        }
    }

    const int gm0 = bm * 128 + ty * 8;
    const int gn0 = bn * 128 + tx * 8;
    float bb[8];
    if (bias) {
        *(float4*)(bb)     = *(const float4*)(bias + gn0);
        *(float4*)(bb + 4) = *(const float4*)(bias + gn0 + 4);
    } else {
#pragma unroll
        for (int j = 0; j < 8; j++) bb[j] = 0.f;
    }
#pragma unroll
    for (int i = 0; i < 8; i++) {
        float cv[8];
#pragma unroll
        for (int jp = 0; jp < 4; jp++) {
            float lo, hi;
            asm("mov.b64 {%0, %1}, %2;" : "=f"(lo), "=f"(hi) : "l"(acc2[i][jp]));
            cv[2 * jp]     = lo + bb[2 * jp];
            cv[2 * jp + 1] = hi + bb[2 * jp + 1];
        }
        float* crow = C + (size_t)(gm0 + i) * N + gn0;
        *(float4*)(crow)     = *(float4*)(cv);
        *(float4*)(crow + 4) = *(float4*)(cv + 4);
    }
}

// ---------------------------------------------------------------------------
// init: th[0] = tanh(x[0]); reset grid barrier
// ---------------------------------------------------------------------------
__global__ void __launch_bounds__(256) init_kernel()
{
    int i = blockIdx.x * blockDim.x + threadIdx.x;
    if (i < B_SZ * H_SZ) g_th[i] = tanhf(g_x[i]);
    if (i == 0) g_bar = 0u;
}

// ---------------------------------------------------------------------------
// Persistent recurrence scan (unchanged — measured fast)
// ---------------------------------------------------------------------------
extern __shared__ float smem_dyn[];

__global__ void __launch_bounds__(256) rnn_scan_kernel(const float* __restrict__ W_hh)
{
    float* sh_th = smem_dyn;
    float* psum  = smem_dyn + 16 * 1024;

    const int tid = threadIdx.x;
    const int n   = tid & 15;
    const int kc  = tid >> 4;
    const int n0  = blockIdx.x * 16;

    unsigned long long wq[32];
    {
        const ulonglong2* wp =
            (const ulonglong2*)(W_hh + (size_t)(n0 + n) * H_SZ + kc * 64);
#pragma unroll
        for (int t = 0; t < 16; ++t) {
            ulonglong2 u = wp[t];
            wq[2 * t]     = u.x;
            wq[2 * t + 1] = u.y;
        }
    }

    const int rb = tid >> 4;
    const int rn = tid & 15;
    unsigned* barp = &g_bar;

    for (int s = 1; s < S_LEN; ++s) {
        __syncthreads();
        if (tid == 0) {
            __threadfence();
            atomicAdd(barp, 1u);
            const unsigned target = 64u * (unsigned)s;
            unsigned v;
            do {
                asm volatile("ld.acquire.gpu.u32 %0, [%1];" : "=r"(v) : "l"(barp));
            } while (v < target);
        }
        __syncthreads();

        const float xv = g_x[(size_t)s * B_SZ * H_SZ + rb * H_SZ + n0 + rn];

        {
            const float4* src = (const float4*)(g_th + (size_t)(s - 1) * B_SZ * H_SZ);
            float4* dst = (float4*)sh_th;
#pragma unroll
            for (int t = 0; t < 16; ++t)
                dst[tid + 256 * t] = src[tid + 256 * t];
        }
        __syncthreads();

#pragma unroll 1
        for (int b = 0; b < 16; ++b) {
            const ulonglong2* tp = (const ulonglong2*)(sh_th + b * H_SZ + kc * 64);
            unsigned long long s0 = 0ull, s1 = 0ull;
#pragma unroll
            for (int t = 0; t < 16; ++t) {
                ulonglong2 u = tp[t];
                asm("fma.rn.f32x2 %0, %1, %2, %0;" : "+l"(s0) : "l"(wq[2 * t]),     "l"(u.x));
                asm("fma.rn.f32x2 %0, %1, %2, %0;" : "+l"(s1) : "l"(wq[2 * t + 1]), "l"(u.y));
            }
            float p0, p1, p2, p3;
            asm("mov.b64 {%0, %1}, %2;" : "=f"(p0), "=f"(p1) : "l"(s0));
            asm("mov.b64 {%0, %1}, %2;" : "=f"(p2), "=f"(p3) : "l"(s1));
            psum[kc * 256 + b * 16 + n] = (p0 + p1) + (p2 + p3);
        }
        __syncthreads();

        float acc = xv;
#pragma unroll
        for (int k2 = 0; k2 < 16; ++k2)
            acc += psum[k2 * 256 + rb * 16 + rn];
        g_th[(size_t)s * B_SZ * H_SZ + rb * H_SZ + n0 + rn] = tanhf(acc);
    }
}

// ---------------------------------------------------------------------------
// hi/lo bf16 split conversions
// ---------------------------------------------------------------------------
__global__ void __launch_bounds__(256) convert_wo_kernel(const float* __restrict__ W_out)
{
    size_t total = (size_t)V_SZ * H_SZ;
    size_t stride = (size_t)gridDim.x * blockDim.x;
    for (size_t i = (size_t)blockIdx.x * blockDim.x + threadIdx.x; i < total; i += stride) {
        float x = W_out[i];
        __nv_bfloat16 hi = __float2bfloat16(x);
        __nv_bfloat16 lo = __float2bfloat16(x - __bfloat162float(hi));
        g_wo_hi[i] = hi;
        g_wo_lo[i] = lo;
    }
}

__global__ void __launch_bounds__(256) convert_th_kernel()
{
    size_t total = (size_t)M_SZ * H_SZ;
    size_t i = (size_t)blockIdx.x * blockDim.x + threadIdx.x;
    if (i < total) {
        float x = g_th[i];
        __nv_bfloat16 hi = __float2bfloat16(x);
        __nv_bfloat16 lo = __float2bfloat16(x - __bfloat162float(hi));
        g_th_hi[i] = hi;
        g_th_lo[i] = lo;
    }
}

// ---------------------------------------------------------------------------
// HMMA (mma.sync) bf16-split output GEMM:
//   C[4096, 32000] = th[4096,1024] @ W_out[32000,1024]^T + b_out
// BM=128, BN=128, BK=64. 8 warps = 2(M) x 4(N); warp tile 64x32.
// 3 terms per k-slice: Ah*Bh + Ah*Bl + Al*Bh (fp32 accum).
// cp.async double-buffered, SW128-swizzled smem, ldmatrix operand loads.
// NOTE: B is stored [n][k] (k contiguous) -> NON-trans ldmatrix gives the
// mma.row.col B fragment directly (lane l: n=l>>2, k=(l&3)*2,+1).
// ---------------------------------------------------------------------------
#define KCHUNK   64
#define NKC      (H_SZ / KCHUNK)     // 16
#define TILE_SZ  (128 * 128)         // bytes per bf16 tile (128 rows x 64 bf16)
#define STAGE_SZ (4 * TILE_SZ)       // Ah Al Bh Bl = 64 KB
#define MMA_SMEM (1024 + 2 * STAGE_SZ)

extern __shared__ char smem_raw[];

__device__ __forceinline__ void fill_stage(
    uint32_t sbase, int stage, int kc, int m0, int n0, int tid)
{
    const uint32_t st = sbase + (uint32_t)stage * STAGE_SZ;
#pragma unroll
    for (int i = 0; i < 4; ++i) {
        int ch = tid + 256 * i;
        int r = ch >> 3, c = ch & 7;
        uint32_t so = SMEM_SWIZZLE_128B((uint32_t)(r * 128 + c * 16));
        size_t ga = (size_t)(m0 + r) * H_SZ + kc * KCHUNK + c * 8;
        cp16(st + so,               g_th_hi + ga);
        cp16(st + TILE_SZ + so,     g_th_lo + ga);
        size_t gb = (size_t)(n0 + r) * H_SZ + kc * KCHUNK + c * 8;
        cp16(st + 2 * TILE_SZ + so, g_wo_hi + gb);
        cp16(st + 3 * TILE_SZ + so, g_wo_lo + gb);
    }
}

__global__ void __launch_bounds__(256, 1) mma_out_kernel(
    const float* __restrict__ b_out, float* __restrict__ C)
{
    const uint32_t sbase = (smem_to_u32(smem_raw) + 1023u) & ~1023u;

    const int tid    = threadIdx.x;
    const int wid    = tid >> 5;
    const int lane   = tid & 31;
    const int warp_m = wid & 1;       // 0..1 -> 64 rows
    const int warp_n = wid >> 1;      // 0..3 -> 32 cols

    const int m0 = blockIdx.y * 128;
    const int n0 = blockIdx.x * 128;

    // ldmatrix per-lane address components (all NON-trans)
    // A: mat = lane>>3 ; row += (mat&1)*8 ; kbyte += (mat>>1)*16
    //   -> r0 = m0-7/k0-7 (a0), r1 = m8-15/k0-7 (a1), r2 = m0-7/k8-15 (a2), r3 (a3)
    const int a_row = warp_m * 64 + ((lane >> 3) & 1) * 8 + (lane & 7);
    const int a_kb  = ((lane >> 4) & 1) * 16;
    // B: mat = lane>>3 ; n += (mat>>1)*8 ; kbyte += (mat&1)*16
    //   -> r0 = n0-7/k0-7 (b0), r1 = n0-7/k8-15 (b1), r2/r3 = n8-15 pair
    const int b_row = warp_n * 32 + ((lane >> 4) & 1) * 8 + (lane & 7);
    const int b_kb  = ((lane >> 3) & 1) * 16;

    float acc[4][4][4];
#pragma unroll
    for (int i = 0; i < 4; i++)
#pragma unroll
        for (int j = 0; j < 4; j++)
#pragma unroll
            for (int k = 0; k < 4; k++) acc[i][j][k] = 0.f;

    fill_stage(sbase, 0, 0, m0, n0, tid);
    cp_commit();

    for (int kc = 0; kc < NKC; ++kc) {
        const int buf = kc & 1;
        if (kc + 1 < NKC) {
            fill_stage(sbase, buf ^ 1, kc + 1, m0, n0, tid);
            cp_commit();
            cp_wait<1>();
        } else {
            cp_wait<0>();
        }
        __syncthreads();

        const uint32_t st = sbase + (uint32_t)buf * STAGE_SZ;

#pragma unroll
        for (int ks = 0; ks < 4; ++ks) {
            uint32_t ah[4][4], al[4][4];
#pragma unroll
            for (int mt = 0; mt < 4; ++mt) {
                uint32_t off = (uint32_t)((a_row + mt * 16) * 128 + ks * 32 + a_kb);
                uint32_t so  = SMEM_SWIZZLE_128B(off);
                ldsm_x4(ah[mt], st + so);
                ldsm_x4(al[mt], st + TILE_SZ + so);
            }
            uint32_t bh[2][4], bl[2][4];   // each x4 = two n8 frags
#pragma unroll
            for (int np = 0; np < 2; ++np) {
                uint32_t off = (uint32_t)((b_row + np * 16) * 128 + ks * 32 + b_kb);
                uint32_t so  = SMEM_SWIZZLE_128B(off);
                ldsm_x4(bh[np], st + 2 * TILE_SZ + so);
                ldsm_x4(bl[np], st + 3 * TILE_SZ + so);
            }
#pragma unroll
            for (int mt = 0; mt < 4; ++mt) {
#pragma unroll
                for (int nt = 0; nt < 4; ++nt) {
                    const uint32_t* bhf = &bh[nt >> 1][(nt & 1) * 2];
                    const uint32_t* blf = &bl[nt >> 1][(nt & 1) * 2];
                    mma16816(acc[mt][nt], ah[mt], bhf);
                    mma16816(acc[mt][nt], ah[mt], blf);
                    mma16816(acc[mt][nt], al[mt], bhf);
                }
            }
        }
        __syncthreads();
    }

    // epilogue
    const int group = lane >> 2;
    const int tig   = lane & 3;
#pragma unroll
    for (int nt = 0; nt < 4; ++nt) {
        const int col = n0 + warp_n * 32 + nt * 8 + tig * 2;
        const float2 bv = *(const float2*)(b_out + col);
#pragma unroll
        for (int mt = 0; mt < 4; ++mt) {
            const int row0 = m0 + warp_m * 64 + mt * 16 + group;
            float2 v0, v1;
            v0.x = acc[mt][nt][0] + bv.x;
            v0.y = acc[mt][nt][1] + bv.y;
            v1.x = acc[mt][nt][2] + bv.x;
            v1.y = acc[mt][nt][3] + bv.y;
            *(float2*)(C + (size_t)row0 * V_SZ + col)       = v0;
            *(float2*)(C + (size_t)(row0 + 8) * V_SZ + col) = v1;
        }
    }
}

// ---------------------------------------------------------------------------
// kernel_launch
// ---------------------------------------------------------------------------
extern "C" void kernel_launch(void* const* d_in, const int* in_sizes, int n_in,
                              void* d_out, int out_size)
{
    (void)in_sizes; (void)n_in; (void)out_size;
    const int*   tokens = (const int*)  d_in[0];
    const float* emb    = (const float*)d_in[1];
    const float* W_in   = (const float*)d_in[2];
    const float* W_hh   = (const float*)d_in[3];
    const float* W_out  = (const float*)d_in[4];
    const float* b_out  = (const float*)d_in[5];
    float* out = (float*)d_out;

    float* gx = nullptr;
    cudaGetSymbolAddress((void**)&gx, g_x);

    // 0) W_out hi/lo bf16 split
    convert_wo_kernel<<<2048, 256>>>(W_out);

    // 1) x = gather(emb) @ W_in^T
    sgemm128_nt<true><<<dim3(H_SZ / 128, M_SZ / 128), 256>>>(
        emb, W_in, nullptr, tokens, gx, H_SZ, E_SZ);

    // 2) th[0] = tanh(x[0]); reset barrier
    init_kernel<<<(B_SZ * H_SZ + 255) / 256, 256>>>();

    // 3) persistent recurrence
    const int scan_smem = (16 * 1024 + 16 * 16 * 16) * (int)sizeof(float);
    cudaFuncSetAttribute(rnn_scan_kernel,
                         cudaFuncAttributeMaxDynamicSharedMemorySize, scan_smem);
    rnn_scan_kernel<<<H_SZ / 16, 256, scan_smem>>>(W_hh);

    // 4) th hi/lo bf16 split
    convert_th_kernel<<<(M_SZ * H_SZ + 255) / 256, 256>>>();

    // 5) logits = th @ W_out^T + b_out via HMMA (3-term bf16 split)
    cudaFuncSetAttribute(mma_out_kernel,
                         cudaFuncAttributeMaxDynamicSharedMemorySize, MMA_SMEM);
    mma_out_kernel<<<dim3(V_SZ / 128, M_SZ / 128), 256, MMA_SMEM>>>(b_out, out);
}